// round 5
// baseline (speedup 1.0000x reference)
#include <cuda_runtime.h>
#include <cstdint>

// Shapes (fixed):
//   x_main: [1, T=128, M=512, K=256] fp32
//   x_aux : [K=256, T=128, Da=256]   fp32
//   W     : [Da=256, E=512]          fp32
//   b     : [E=512]                  fp32
//   out   : [1,T,M,E,1] = [128,512,512] fp32
//
// Stage 1 (per t): scratch[t][e][perm(k)] = relu( sum_d W[d][e]*x_aux[k][t][d] + b[e] )
// Stage 2 (per t): out[t][m][e] = sum_k x_main[t][m][k] * scratch[t][e][k]
//
// mma.sync.m16n8k8 tf32.  All fragment loads are ld.shared.v4 enabled by:
//  - k-permutation within 16-k groups: p0(k) = 4*(k&3) | ((k>>2)&1) | 2*((k>>3)&1)
//    => fragment k-set {tg, tg+4, tg+8, tg+12} is contiguous.
//  - row-major tiles stored [kh(2)][row(128)][16] (row stride 64B) with per-row
//    rotation +4*(row&3): v4 reads conflict-free (row parity splits banks),
//    permuted STS writes are only 2-way conflicted.
//  - W pre-permuted into fragment-cell layout (1 v4 = 1 whole A fragment).
//  - scratch written permuted by stage-1 epilogue => stage-2 B cp.asyncs v4-ready.
// All values rna-rounded to tf32 exactly once (numerics identical to R3/R4).

__device__ float g_scratch[128 * 512 * 256];  // [T][E][K-perm], 64 MB
__device__ float g_Wp[256 * 512];             // W in fragment-cell layout

static constexpr int TILE_B = 2 * 128 * 16 * 4;      // 16 KB per operand tile
static constexpr int SMEM_TOTAL = 4 * TILE_B;        // 64 KB -> 2 CTAs/SM

__device__ __forceinline__ uint32_t smem_u32(const void* p) {
    uint32_t a;
    asm("{ .reg .u64 t; cvta.to.shared.u64 t, %1; cvt.u32.u64 %0, t; }" : "=r"(a) : "l"(p));
    return a;
}
__device__ __forceinline__ float f2tf32f(float f) {
    uint32_t r;
    asm("cvt.rna.tf32.f32 %0, %1;" : "=r"(r) : "f"(f));
    return __uint_as_float(r);
}
__device__ __forceinline__ int permcol(int k, int e) {
    const int k4 = k & 15;
    const int p0 = ((k4 & 3) << 2) | ((k4 >> 2) & 1) | (((k4 >> 3) & 1) << 1);
    return (k & ~15) | ((p0 + ((e & 3) << 2)) & 15);
}
#define CP_ASYNC16(dst32, src) \
    asm volatile("cp.async.cg.shared.global [%0], [%1], 16;" :: "r"(dst32), "l"(src))
#define CP_COMMIT() asm volatile("cp.async.commit_group;" ::: "memory")
#define CP_WAIT0()  asm volatile("cp.async.wait_group 0;" ::: "memory")
#define LDS128(r0, r1, r2, r3, addr) \
    asm volatile("ld.shared.v4.b32 {%0,%1,%2,%3}, [%4];" \
                 : "=r"(r0), "=r"(r1), "=r"(r2), "=r"(r3) : "r"(addr))
#define STS32(addr, v) \
    asm volatile("st.shared.b32 [%0], %1;" :: "r"(addr), "r"(v) : "memory")

__device__ __forceinline__ void mma_tf32(float* d, const uint32_t* a,
                                         uint32_t b0, uint32_t b1) {
    asm volatile(
        "mma.sync.aligned.m16n8k8.row.col.f32.tf32.tf32.f32 "
        "{%0,%1,%2,%3}, {%4,%5,%6,%7}, {%8,%9}, {%0,%1,%2,%3};"
        : "+f"(d[0]), "+f"(d[1]), "+f"(d[2]), "+f"(d[3])
        : "r"(a[0]), "r"(a[1]), "r"(a[2]), "r"(a[3]), "r"(b0), "r"(b1));
}

// Prologue: round W to tf32 and re-layout into fragment cells:
// g_Wp[kt(8)][M16(32)][ks(4)][lane(32)][4], cell = {(e,d),(e+8,d),(e,d+4),(e+8,d+4)}
__global__ void w_perm_kernel(const float* __restrict__ W) {
    const int c = blockIdx.x * 256 + threadIdx.x;   // 0..32767 cells
    const int kt   = c >> 12;
    const int rem  = c & 4095;
    const int M16  = rem >> 7;
    const int ks   = (rem >> 5) & 3;
    const int lane = rem & 31;
    const int g  = lane >> 2, tg = lane & 3;
    const int e  = M16 * 16 + g;
    const int d  = kt * 32 + ks * 8 + tg;
    float4 v;
    v.x = f2tf32f(W[(size_t)d * 512 + e]);
    v.y = f2tf32f(W[(size_t)d * 512 + e + 8]);
    v.z = f2tf32f(W[(size_t)(d + 4) * 512 + e]);
    v.w = f2tf32f(W[(size_t)(d + 4) * 512 + e + 8]);
    reinterpret_cast<float4*>(g_Wp)[c] = v;
}

template <bool STAGE1>
__global__ void __launch_bounds__(256, 2)
slam_mma_kernel(const float* __restrict__ Aglob, const float* __restrict__ Bglob,
                const float* __restrict__ bias, float* __restrict__ Cglob) {
    extern __shared__ __align__(16) char smem[];
    const uint32_t sb = smem_u32(smem);
    const int tid = threadIdx.x;
    const int wid = tid >> 5;
    const int lid = tid & 31;
    const int g  = lid >> 2;
    const int tg = lid & 3;
    const int warp_m = (wid & 1) * 64;
    const int warp_n = (wid >> 1) * 32;
    const int t  = blockIdx.z;
    const int m0 = blockIdx.y * 128;
    const int n0 = blockIdx.x * 128;

    // cp.async operand: stage1 -> A (g_Wp cells); stage2 -> B (permuted scratch)
    // LDG-staged operand: stage1 -> B (x_aux);    stage2 -> A (x_main)
    const float* ld_src;  size_t ld_rstride;
    const float* cp_src = nullptr;
    float* C;
    if (STAGE1) {
        ld_src = Bglob + (size_t)t * 256;            // x_aux[.,t,.], rows k
        ld_rstride = 128 * 256;
        C = g_scratch + (size_t)t * 512 * 256;       // [e][k-perm]
    } else {
        ld_src = Aglob + (size_t)t * 512 * 256;      // x_main[t], rows m
        ld_rstride = 256;
        cp_src = g_scratch + (size_t)t * 512 * 256;  // rows e, k-perm baked in
        C = Cglob + (size_t)t * 512 * 512;
    }

    const uint32_t aoff[2] = {sb, sb + TILE_B};
    const uint32_t boff[2] = {sb + 2 * TILE_B, sb + 3 * TILE_B};

    // ---- cp.async tile ----
    auto cpasync_tile = [&](int kt, int buf) {
        if (STAGE1) {
            // Wp tile: contiguous 16 KB region, fragment-cell layout
            const float* src = g_Wp + (size_t)kt * 16384 + (size_t)(m0 >> 4) * 512;
#pragma unroll
            for (int i = 0; i < 4; ++i) {
                const int idx = tid + i * 256;       // 0..1023
                CP_ASYNC16(aoff[buf] + idx * 16, src + idx * 4);
            }
        } else {
            // scratch tile rows -> [kh][row][16]
#pragma unroll
            for (int i = 0; i < 4; ++i) {
                const int idx = tid + i * 256;
                const int row = idx >> 3;            // 0..127
                const int kh  = (idx >> 2) & 1;
                const int c   = idx & 3;
                CP_ASYNC16(boff[buf] + kh * 8192 + row * 64 + c * 16,
                           cp_src + (size_t)(n0 + row) * 256 + kt * 32 + kh * 16 + c * 4);
            }
        }
    };

    // ---- register-staged LDG of the other operand ----
    const int srow = tid >> 3;   // 0..31 within warp-block; overall 0..31? tid>>3: 0..31
    const int sch  = tid & 7;    // float4 chunk along reduction dim
    auto ldg_tile = [&](int kt, float4 (&r)[4]) {
        const int base_row = STAGE1 ? n0 : m0;
#pragma unroll
        for (int i = 0; i < 4; ++i)
            r[i] = *reinterpret_cast<const float4*>(
                ld_src + (size_t)(base_row + srow + i * 32) * ld_rstride
                       + kt * 32 + sch * 4);
    };
    // permuted STS: value j (k = kt*32 + 4*sch + j) of row (srow + 32i)
    auto sts_staged = [&](float4 (&r)[4], int buf) {
        const uint32_t dbase = (STAGE1 ? boff[buf] : aoff[buf])
                             + ((sch >> 2) << 13) + srow * 64;
        const int prot = (srow & 3) << 2;
#pragma unroll
        for (int i = 0; i < 4; ++i) {
            const uint32_t rb = dbase + i * 2048;
            float v[4] = {r[i].x, r[i].y, r[i].z, r[i].w};
#pragma unroll
            for (int j = 0; j < 4; ++j) {
                const int p = ((j << 2) + (sch & 3) + prot) & 15;
                STS32(rb + p * 4, __float_as_uint(f2tf32f(v[j])));
            }
        }
    };

    float acc[4][4][4];
#pragma unroll
    for (int mi = 0; mi < 4; ++mi)
#pragma unroll
        for (int nj = 0; nj < 4; ++nj)
#pragma unroll
            for (int q = 0; q < 4; ++q) acc[mi][nj][q] = 0.0f;

    auto compute_tile = [&](int buf) {
        const uint32_t ab = aoff[buf], bb = boff[buf];
#pragma unroll
        for (int kh = 0; kh < 2; ++kh) {
            uint32_t bv[4][4];
#pragma unroll
            for (int nj = 0; nj < 4; ++nj) {
                const int n_ = warp_n + 8 * nj + g;
                const uint32_t addr = bb + (kh << 13) + n_ * 64
                                    + (((tg + (n_ & 3)) & 3) << 4);
                LDS128(bv[nj][0], bv[nj][1], bv[nj][2], bv[nj][3], addr);
            }
#pragma unroll
            for (int mi = 0; mi < 4; ++mi) {
                uint32_t a0[4], a1[4];
                if (STAGE1) {
                    const int M16l = (warp_m >> 4) + mi;
                    const uint32_t base =
                        ab + (uint32_t)(((M16l * 4 + 2 * kh) * 32 + lid) << 4);
                    LDS128(a0[0], a0[1], a0[2], a0[3], base);
                    LDS128(a1[0], a1[1], a1[2], a1[3], base + 512);
                } else {
                    const int r_ = warp_m + 16 * mi + g;
                    const uint32_t rot = ((tg + (r_ & 3)) & 3) << 4;
                    uint32_t ar[4], ar8[4];
                    LDS128(ar[0], ar[1], ar[2], ar[3],
                           ab + (kh << 13) + r_ * 64 + rot);
                    LDS128(ar8[0], ar8[1], ar8[2], ar8[3],
                           ab + (kh << 13) + (r_ + 8) * 64 + rot);
                    a0[0] = ar[0]; a0[1] = ar8[0]; a0[2] = ar[1]; a0[3] = ar8[1];
                    a1[0] = ar[2]; a1[1] = ar8[2]; a1[2] = ar[3]; a1[3] = ar8[3];
                }
#pragma unroll
                for (int nj = 0; nj < 4; ++nj) {
                    mma_tf32(acc[mi][nj], a0, bv[nj][0], bv[nj][1]);
                    mma_tf32(acc[mi][nj], a1, bv[nj][2], bv[nj][3]);
                }
            }
        }
    };

    // ---- pipelined mainloop: 8 k-tiles of 32, double-buffered ----
    float4 stage_regs[4];
    cpasync_tile(0, 0);
    CP_COMMIT();
    ldg_tile(0, stage_regs);
    CP_WAIT0();
    sts_staged(stage_regs, 0);
    __syncthreads();

    int buf = 0;
#pragma unroll 1
    for (int kt = 0; kt < 8; ++kt) {
        if (kt < 7) {
            cpasync_tile(kt + 1, buf ^ 1);
            CP_COMMIT();
            ldg_tile(kt + 1, stage_regs);
        }
        compute_tile(buf);
        if (kt < 7) {
            CP_WAIT0();
            sts_staged(stage_regs, buf ^ 1);
            __syncthreads();
        }
        buf ^= 1;
    }

    // ---- epilogue ----
    if (STAGE1) {
#pragma unroll
        for (int mi = 0; mi < 4; ++mi) {
            const int r0 = m0 + warp_m + 16 * mi + g;   // e rows
            const int r1 = r0 + 8;
            const float bv0 = bias[r0], bv1 = bias[r1];
            float* C0 = C + (size_t)r0 * 256;
            float* C1 = C + (size_t)r1 * 256;
#pragma unroll
            for (int nj = 0; nj < 4; ++nj) {
                const int col = n0 + warp_n + 8 * nj + 2 * tg;   // k cols
                C0[permcol(col,     r0)] = f2tf32f(fmaxf(acc[mi][nj][0] + bv0, 0.0f));
                C0[permcol(col + 1, r0)] = f2tf32f(fmaxf(acc[mi][nj][1] + bv0, 0.0f));
                C1[permcol(col,     r1)] = f2tf32f(fmaxf(acc[mi][nj][2] + bv1, 0.0f));
                C1[permcol(col + 1, r1)] = f2tf32f(fmaxf(acc[mi][nj][3] + bv1, 0.0f));
            }
        }
    } else {
#pragma unroll
        for (int mi = 0; mi < 4; ++mi) {
            const int r0 = m0 + warp_m + 16 * mi + g;
            const int r1 = r0 + 8;
#pragma unroll
            for (int nj = 0; nj < 4; ++nj) {
                const int col = n0 + warp_n + 8 * nj + 2 * tg;
                float2 v0, v1;
                v0.x = acc[mi][nj][0]; v0.y = acc[mi][nj][1];
                v1.x = acc[mi][nj][2]; v1.y = acc[mi][nj][3];
                *reinterpret_cast<float2*>(C + (size_t)r0 * 512 + col) = v0;
                *reinterpret_cast<float2*>(C + (size_t)r1 * 512 + col) = v1;
            }
        }
    }
}

extern "C" void kernel_launch(void* const* d_in, const int* in_sizes, int n_in,
                              void* d_out, int out_size) {
    const float* x_main = (const float*)d_in[0];  // [1,128,512,256]
    const float* x_aux  = (const float*)d_in[1];  // [256,128,256]
    const float* W      = (const float*)d_in[2];  // [256,512]
    const float* b      = (const float*)d_in[3];  // [512]
    float* out = (float*)d_out;                   // [128,512,512]

    cudaFuncSetAttribute(slam_mma_kernel<true>,
                         cudaFuncAttributeMaxDynamicSharedMemorySize, SMEM_TOTAL);
    cudaFuncSetAttribute(slam_mma_kernel<false>,
                         cudaFuncAttributeMaxDynamicSharedMemorySize, SMEM_TOTAL);

    // W -> tf32 fragment-cell layout (once per launch)
    w_perm_kernel<<<128, 256>>>(W);
    // Stage 1: per-t  D[e(512) x k(256)] = W^T x_aux[.,t,.]^T (+bias, relu) -> perm scratch
    slam_mma_kernel<true><<<dim3(2, 4, 128), 256, SMEM_TOTAL>>>(nullptr, x_aux, b, nullptr);
    // Stage 2: per-t  D[m(512) x e(512)] = x_main[t] . scratch[t]^T -> out
    slam_mma_kernel<false><<<dim3(4, 4, 128), 256, SMEM_TOTAL>>>(x_main, nullptr, nullptr, out);
}

// round 6
// speedup vs baseline: 1.1131x; 1.1131x over previous
#include <cuda_runtime.h>
#include <cstdint>

// Shapes (fixed):
//   x_main: [1, T=128, M=512, K=256] fp32
//   x_aux : [K=256, T=128, Da=256]   fp32
//   W     : [Da=256, E=512]          fp32
//   b     : [E=512]                  fp32
//   out   : [1,T,M,E,1] = [128,512,512] fp32
//
// Stage 1 (per t): scratch[t][e][pcol(k,e)] = relu( sum_d W[d][e]*x_aux[k][t][d] + b[e] )
//   (R4 mainloop verbatim; epilogue stores with per-row permutation pcol)
// Stage 2 (per t): out[t][m][e] = sum_k x_main[t][m][k] * scratch[t][e][k]
//   B (scratch): cp.async verbatim (layout is v2-fragment-ready, xor-swizzled by row).
//   A (x_main): LDG+cvt+STS into 10-float-group padded rows (160B) — conflict-free
//   STS and conflict-free v2 fragment reads.
// All values rna-rounded to tf32 exactly once (numerics identical to R3/R4).

__device__ __align__(16) float g_scratch[128 * 512 * 256];  // [T][E][K-perm], 64 MB
__device__ __align__(16) float g_Wtf32[256 * 512];          // W pre-rounded (natural layout)

__device__ __forceinline__ uint32_t smem_u32(const void* p) {
    uint32_t a;
    asm("{ .reg .u64 t; cvta.to.shared.u64 t, %1; cvt.u32.u64 %0, t; }" : "=r"(a) : "l"(p));
    return a;
}
__device__ __forceinline__ float f2tf32f(float f) {
    uint32_t r;
    asm("cvt.rna.tf32.f32 %0, %1;" : "=r"(r) : "f"(f));
    return __uint_as_float(r);
}
// permuted column within each 32-k tile: group(k8) ^= (e&3); pairs (k,k+4) interleaved
__device__ __forceinline__ int pcol(int k, int e) {
    return (k & ~31) | ((((k >> 3) & 3) ^ (e & 3)) << 3) | ((k & 3) << 1) | ((k >> 2) & 1);
}
#define CP_ASYNC16(dst32, src) \
    asm volatile("cp.async.cg.shared.global [%0], [%1], 16;" :: "r"(dst32), "l"(src))
#define CP_COMMIT() asm volatile("cp.async.commit_group;" ::: "memory")
#define CP_WAIT0()  asm volatile("cp.async.wait_group 0;" ::: "memory")
#define LDS64(r0, r1, addr) \
    asm volatile("ld.shared.v2.b32 {%0,%1}, [%2];" : "=r"(r0), "=r"(r1) : "r"(addr))
#define STS32(addr, v) \
    asm volatile("st.shared.b32 [%0], %1;" :: "r"(addr), "r"(v) : "memory")
#define STS128(addr, v) \
    asm volatile("st.shared.v4.b32 [%0], {%1,%2,%3,%4};" \
                 :: "r"(addr), "f"(v.x), "f"(v.y), "f"(v.z), "f"(v.w) : "memory")

__device__ __forceinline__ void mma_tf32(float* d, uint32_t a0, uint32_t a1,
                                         uint32_t a2, uint32_t a3,
                                         uint32_t b0, uint32_t b1) {
    asm volatile(
        "mma.sync.aligned.m16n8k8.row.col.f32.tf32.tf32.f32 "
        "{%0,%1,%2,%3}, {%4,%5,%6,%7}, {%8,%9}, {%0,%1,%2,%3};"
        : "+f"(d[0]), "+f"(d[1]), "+f"(d[2]), "+f"(d[3])
        : "r"(a0), "r"(a1), "r"(a2), "r"(a3), "r"(b0), "r"(b1));
}

// Pre-pass: round W to tf32 once (natural [d][e] layout)
__global__ void w_round_kernel(const float* __restrict__ W) {
    const int i = blockIdx.x * 256 + threadIdx.x;   // 32768 float4
    float4 v = reinterpret_cast<const float4*>(W)[i];
    v.x = f2tf32f(v.x); v.y = f2tf32f(v.y); v.z = f2tf32f(v.z); v.w = f2tf32f(v.w);
    reinterpret_cast<float4*>(g_Wtf32)[i] = v;
}

// ============================ Stage 1 (R4 + permuted epilogue) ============================
static constexpr int S1_TILE = 18432;                       // per-operand tile region
static constexpr int S1_SMEM = 4 * S1_TILE;                 // 73728

__global__ void __launch_bounds__(256, 2)
slam_stage1(const float* __restrict__ x_aux, const float* __restrict__ bias) {
    extern __shared__ __align__(16) char smem[];
    const uint32_t sb = smem_u32(smem);
    const int tid = threadIdx.x, wid = tid >> 5, lid = tid & 31;
    const int g = lid >> 2, tg = lid & 3;
    const int warp_m = (wid & 1) * 64, warp_n = (wid >> 1) * 32;
    const int t = blockIdx.z, m0 = blockIdx.y * 128, n0 = blockIdx.x * 128;

    const float* Bsrc = x_aux + (size_t)t * 256;        // rows k, stride 32768
    float* C = g_scratch + (size_t)t * 512 * 256;       // [e][k-perm]

    const uint32_t aoff[2] = {sb, sb + S1_TILE};
    const uint32_t boff[2] = {sb + 2 * S1_TILE, sb + 3 * S1_TILE};

    auto cpasync_tile = [&](int kt, int buf) {
        // W tile [32 d][128 e], ld=136 floats (544 B rows)
#pragma unroll
        for (int i = 0; i < 4; ++i) {
            const int idx = tid + i * 256;
            const int row = idx >> 5, ch = idx & 31;
            CP_ASYNC16(aoff[buf] + row * 544 + ch * 16,
                       g_Wtf32 + (size_t)(kt * 32 + row) * 512 + m0 + ch * 4);
        }
    };
    const int srow = tid >> 3, sch = tid & 7;
    auto ldg_tile = [&](int kt, float4 (&r)[4]) {
#pragma unroll
        for (int i = 0; i < 4; ++i)
            r[i] = *reinterpret_cast<const float4*>(
                Bsrc + (size_t)(n0 + srow + i * 32) * (128 * 256) + kt * 32 + sch * 4);
    };
    auto sts_tile = [&](float4 (&r)[4], int buf) {
        const uint32_t base = boff[buf] + srow * 144 + sch * 16;
#pragma unroll
        for (int i = 0; i < 4; ++i) {
            float4 v = r[i];
            v.x = f2tf32f(v.x); v.y = f2tf32f(v.y);
            v.z = f2tf32f(v.z); v.w = f2tf32f(v.w);
            STS128(base + i * 32 * 144, v);
        }
    };

    float acc[4][4][4];
#pragma unroll
    for (int mi = 0; mi < 4; ++mi)
#pragma unroll
        for (int nj = 0; nj < 4; ++nj)
#pragma unroll
            for (int q = 0; q < 4; ++q) acc[mi][nj][q] = 0.0f;

    auto compute_tile = [&](int buf) {
        const float* As = (const float*)(smem + (buf ? S1_TILE : 0));
        const float* Bs = (const float*)(smem + 2 * S1_TILE + (buf ? S1_TILE : 0));
#pragma unroll
        for (int ks = 0; ks < 4; ++ks) {
            const int k8 = ks * 8;
            uint32_t af[4][4], bf[4][2];
#pragma unroll
            for (int mi = 0; mi < 4; ++mi) {
                const int e_ = warp_m + 16 * mi + g;
                const int d_ = k8 + tg;
                af[mi][0] = __float_as_uint(As[d_ * 136 + e_]);
                af[mi][1] = __float_as_uint(As[d_ * 136 + e_ + 8]);
                af[mi][2] = __float_as_uint(As[(d_ + 4) * 136 + e_]);
                af[mi][3] = __float_as_uint(As[(d_ + 4) * 136 + e_ + 8]);
            }
#pragma unroll
            for (int nj = 0; nj < 4; ++nj) {
                const int n_ = warp_n + 8 * nj + g;
                bf[nj][0] = __float_as_uint(Bs[n_ * 36 + k8 + tg]);
                bf[nj][1] = __float_as_uint(Bs[n_ * 36 + k8 + tg + 4]);
            }
#pragma unroll
            for (int mi = 0; mi < 4; ++mi)
#pragma unroll
                for (int nj = 0; nj < 4; ++nj)
                    mma_tf32(acc[mi][nj], af[mi][0], af[mi][1], af[mi][2], af[mi][3],
                             bf[nj][0], bf[nj][1]);
        }
    };

    float4 stage_regs[4];
    cpasync_tile(0, 0);
    CP_COMMIT();
    ldg_tile(0, stage_regs);
    CP_WAIT0();
    sts_tile(stage_regs, 0);
    __syncthreads();

    int buf = 0;
#pragma unroll 1
    for (int kt = 0; kt < 8; ++kt) {
        if (kt < 7) {
            cpasync_tile(kt + 1, buf ^ 1);
            CP_COMMIT();
            ldg_tile(kt + 1, stage_regs);
        }
        compute_tile(buf);
        if (kt < 7) {
            CP_WAIT0();
            sts_tile(stage_regs, buf ^ 1);
            __syncthreads();
        }
        buf ^= 1;
    }

    // epilogue: bias + relu + tf32 round, scattered to permuted columns
#pragma unroll
    for (int mi = 0; mi < 4; ++mi) {
        const int r0 = m0 + warp_m + 16 * mi + g;   // e rows
        const int r1 = r0 + 8;
        const float bv0 = bias[r0], bv1 = bias[r1];
        float* C0 = C + (size_t)r0 * 256;
        float* C1 = C + (size_t)r1 * 256;
#pragma unroll
        for (int nj = 0; nj < 4; ++nj) {
            const int col = n0 + warp_n + 8 * nj + 2 * tg;   // k cols
            C0[pcol(col,     r0)] = f2tf32f(fmaxf(acc[mi][nj][0] + bv0, 0.0f));
            C0[pcol(col + 1, r0)] = f2tf32f(fmaxf(acc[mi][nj][1] + bv0, 0.0f));
            C1[pcol(col,     r1)] = f2tf32f(fmaxf(acc[mi][nj][2] + bv1, 0.0f));
            C1[pcol(col + 1, r1)] = f2tf32f(fmaxf(acc[mi][nj][3] + bv1, 0.0f));
        }
    }
}

// ============================ Stage 2 ============================
static constexpr int S2_A_TILE = 128 * 160;   // 20480 (10-float groups, 160B rows)
static constexpr int S2_B_TILE = 128 * 128;   // 16384 (verbatim permuted scratch rows)
static constexpr int S2_SMEM = 2 * (S2_A_TILE + S2_B_TILE);   // 73728

__global__ void __launch_bounds__(256, 2)
slam_stage2(const float* __restrict__ x_main, float* __restrict__ out) {
    extern __shared__ __align__(16) char smem[];
    const uint32_t sb = smem_u32(smem);
    const int tid = threadIdx.x, wid = tid >> 5, lid = tid & 31;
    const int g = lid >> 2, tg = lid & 3;
    const int warp_m = (wid & 1) * 64, warp_n = (wid >> 1) * 32;
    const int t = blockIdx.z, m0 = blockIdx.y * 128, n0 = blockIdx.x * 128;

    const float* A = x_main + (size_t)t * 512 * 256;
    const float* Bsrc = g_scratch + (size_t)t * 512 * 256;
    float* C = out + (size_t)t * 512 * 512;

    const uint32_t aoff[2] = {sb, sb + S2_A_TILE};
    const uint32_t boff[2] = {sb + 2 * S2_A_TILE, sb + 2 * S2_A_TILE + S2_B_TILE};

    auto cpasync_b = [&](int kt, int buf) {
        // verbatim row copy: permutation already baked into global layout
#pragma unroll
        for (int i = 0; i < 4; ++i) {
            const int idx = tid + i * 256;
            const int row = idx >> 3, ch = idx & 7;
            CP_ASYNC16(boff[buf] + row * 128 + ch * 16,
                       Bsrc + (size_t)(n0 + row) * 256 + kt * 32 + ch * 4);
        }
    };
    const int srow = tid >> 3, sch = tid & 7;
    auto ldg_a = [&](int kt, float4 (&r)[4]) {
#pragma unroll
        for (int i = 0; i < 4; ++i)
            r[i] = *reinterpret_cast<const float4*>(
                A + (size_t)(m0 + srow + i * 32) * 256 + kt * 32 + sch * 4);
    };
    auto sts_a = [&](float4 (&r)[4], int buf) {
        // float idx = row*40 + (sch>>1)*10 + (sch&1) + 2j   (conflict-free)
        const uint32_t base = aoff[buf] + (srow * 40 + (sch >> 1) * 10 + (sch & 1)) * 4;
#pragma unroll
        for (int i = 0; i < 4; ++i) {
            const uint32_t rb = base + i * 32 * 160;
            STS32(rb,      __float_as_uint(f2tf32f(r[i].x)));
            STS32(rb + 8,  __float_as_uint(f2tf32f(r[i].y)));
            STS32(rb + 16, __float_as_uint(f2tf32f(r[i].z)));
            STS32(rb + 24, __float_as_uint(f2tf32f(r[i].w)));
        }
    };

    float acc[4][4][4];
#pragma unroll
    for (int mi = 0; mi < 4; ++mi)
#pragma unroll
        for (int nj = 0; nj < 4; ++nj)
#pragma unroll
            for (int q = 0; q < 4; ++q) acc[mi][nj][q] = 0.0f;

    auto compute_tile = [&](int buf) {
        const uint32_t ab = aoff[buf], bb = boff[buf];
#pragma unroll
        for (int ks = 0; ks < 4; ++ks) {
            uint32_t bf[4][2];
#pragma unroll
            for (int nj = 0; nj < 4; ++nj) {
                const int n_ = warp_n + 8 * nj + g;
                LDS64(bf[nj][0], bf[nj][1],
                      bb + n_ * 128 + ((ks ^ (n_ & 3)) << 5) + (tg << 3));
            }
#pragma unroll
            for (int mi = 0; mi < 4; ++mi) {
                const int r_ = warp_m + 16 * mi + g;
                const uint32_t a_addr = ab + r_ * 160 + ks * 40 + tg * 8;
                uint32_t a0, a1, a2, a3;
                LDS64(a0, a2, a_addr);            // (r_,  tg), (r_,  tg+4)
                LDS64(a1, a3, a_addr + 8 * 160);  // (r_+8,tg), (r_+8,tg+4)
#pragma unroll
                for (int nj = 0; nj < 4; ++nj)
                    mma_tf32(acc[mi][nj], a0, a1, a2, a3, bf[nj][0], bf[nj][1]);
            }
        }
    };

    float4 stage_regs[4];
    cpasync_b(0, 0);
    CP_COMMIT();
    ldg_a(0, stage_regs);
    CP_WAIT0();
    sts_a(stage_regs, 0);
    __syncthreads();

    int buf = 0;
#pragma unroll 1
    for (int kt = 0; kt < 8; ++kt) {
        if (kt < 7) {
            cpasync_b(kt + 1, buf ^ 1);
            CP_COMMIT();
            ldg_a(kt + 1, stage_regs);
        }
        compute_tile(buf);
        if (kt < 7) {
            CP_WAIT0();
            sts_a(stage_regs, buf ^ 1);
            __syncthreads();
        }
        buf ^= 1;
    }

    // epilogue: plain coalesced-ish float2 stores
#pragma unroll
    for (int mi = 0; mi < 4; ++mi) {
        const int r0 = m0 + warp_m + 16 * mi + g;
        const int r1 = r0 + 8;
#pragma unroll
        for (int nj = 0; nj < 4; ++nj) {
            const int col = n0 + warp_n + 8 * nj + 2 * tg;
            float2 v0, v1;
            v0.x = acc[mi][nj][0]; v0.y = acc[mi][nj][1];
            v1.x = acc[mi][nj][2]; v1.y = acc[mi][nj][3];
            *reinterpret_cast<float2*>(C + (size_t)r0 * 512 + col) = v0;
            *reinterpret_cast<float2*>(C + (size_t)r1 * 512 + col) = v1;
        }
    }
}

extern "C" void kernel_launch(void* const* d_in, const int* in_sizes, int n_in,
                              void* d_out, int out_size) {
    const float* x_main = (const float*)d_in[0];  // [1,128,512,256]
    const float* x_aux  = (const float*)d_in[1];  // [256,128,256]
    const float* W      = (const float*)d_in[2];  // [256,512]
    const float* b      = (const float*)d_in[3];  // [512]
    float* out = (float*)d_out;                   // [128,512,512]

    cudaFuncSetAttribute(slam_stage1,
                         cudaFuncAttributeMaxDynamicSharedMemorySize, S1_SMEM);
    cudaFuncSetAttribute(slam_stage2,
                         cudaFuncAttributeMaxDynamicSharedMemorySize, S2_SMEM);

    // W -> tf32 (once per launch)
    w_round_kernel<<<128, 256>>>(W);
    // Stage 1: per-t  D[e(512) x k(256)] = W^T x_aux[.,t,.]^T (+bias, relu) -> permuted scratch
    slam_stage1<<<dim3(2, 4, 128), 256, S1_SMEM>>>(x_aux, b);
    // Stage 2: per-t  D[m(512) x e(512)] = x_main[t] . scratch[t]^T -> out
    slam_stage2<<<dim3(4, 4, 128), 256, S2_SMEM>>>(x_main, out);
}